// round 7
// baseline (speedup 1.0000x reference)
#include <cuda_runtime.h>
#include <cstdint>

// ---------------------------------------------------------------------------
// NeuralSplineFourierFilter: tiny MLP on scalar 'a' -> 16 knots + 18 control
// points -> degree-3 B-spline on a 256^3 grid.
//
// R6: single fused setup kernel builds a 4096-bin table of *re-centered*
// segment cubics (one float4 per bin). Hot loop: 1 LDS.128 + 3 FMA per point.
// Bins containing a knot are flagged in the LSB of p3 -> rare exact slow path.
// ---------------------------------------------------------------------------

#define NSEG 15
#define NBIN 4096

__device__ float4 g_binPoly[NBIN];                   // 64 KB, 16B-aligned by type
__device__ __align__(16) float g_segPoly[NSEG * 4];  // fallback/slow tables
__device__ __align__(16) float g_segLo[NSEG + 1];
__device__ __align__(16) float g_knots[16];

// ---------------------------------------------------------------------------
// Fused setup: MLP + softmax/cumsum + symbolic de Boor (fp64, 15 threads,
// once) + per-bin Taylor-shifted cubics (fp32, 256 threads).
// ---------------------------------------------------------------------------
__global__ void __launch_bounds__(256)
setup_kernel(const float* __restrict__ a_in,
             const float* __restrict__ W1, const float* __restrict__ b1,
             const float* __restrict__ W2, const float* __restrict__ b2,
             const float* __restrict__ Ww, const float* __restrict__ bw,
             const float* __restrict__ Wk, const float* __restrict__ bk)
{
    __shared__ float s_net[32], s_net2[32], s_w[17], s_klog[15];
    __shared__ float s_k[16], s_c[18];
    __shared__ float s_p[NSEG][4];     // segment cubics (local coords u = x-k[s])
    __shared__ float s_lo[NSEG];
    const int t = threadIdx.x;

    if (t < 32) {
        const float a = a_in[0];
        s_net[t] = sinf(fmaf(a, W1[t], b1[t]));
    }
    __syncthreads();
    if (t < 32) {
        float acc = b2[t];
        #pragma unroll
        for (int j = 0; j < 32; ++j) acc = fmaf(s_net[j], W2[j * 32 + t], acc);
        s_net2[t] = sinf(acc);
    }
    __syncthreads();
    if (t < 17) {
        float w = bw[t];
        #pragma unroll
        for (int j = 0; j < 32; ++j) w = fmaf(s_net2[j], Ww[j * 17 + t], w);
        s_w[t] = w;
    }
    if (t >= 32 && t < 47) {           // overlap with the w-row threads
        const int i = t - 32;
        float kk = bk[i];
        #pragma unroll
        for (int j = 0; j < 32; ++j) kk = fmaf(s_net2[j], Wk[j * 15 + i], kk);
        s_klog[i] = kk;
    }
    __syncthreads();
    if (t == 0) {
        float m = s_klog[0];
        for (int i = 1; i < 15; ++i) m = fmaxf(m, s_klog[i]);
        float e[15], sum = 0.f;
        for (int i = 0; i < 15; ++i) { e[i] = expf(s_klog[i] - m); sum += e[i]; }
        const float inv = 1.0f / sum;
        float cs = 0.f;
        s_k[0] = 0.f;
        for (int i = 0; i < 15; ++i) { cs += e[i] * inv; s_k[i + 1] = cs; }
        s_c[0] = 0.f;
        for (int i = 0; i < 17; ++i) s_c[i + 1] = s_w[i];
    }
    __syncthreads();

    if (t < 16) g_knots[t] = s_k[t];

    // Symbolic de Boor: exact cubic per segment in u = x - k[s] (fp64, once).
    if (t < NSEG) {
        double T[22];
        for (int i = 0; i < 3; ++i)  T[i] = 0.0;
        for (int i = 0; i < 16; ++i) T[3 + i] = (double)s_k[i];
        for (int i = 19; i < 22; ++i) T[i] = 1.0;

        const int s = t;
        const double x0 = T[s + 3];

        double D[4][4];
        for (int j = 0; j < 4; ++j) {
            D[j][0] = (double)s_c[s + j];
            D[j][1] = D[j][2] = D[j][3] = 0.0;
        }
        for (int r = 1; r <= 3; ++r) {
            for (int j = 3; j >= r; --j) {
                const double tlo = T[j + s];
                const double thi = T[j + 1 + s + 3 - r];
                const double A = 1.0 / (thi - tlo);
                const double B = A * (x0 - tlo);     // alpha(u) = A*u + B
                double nf[4];
                for (int m2 = 0; m2 < 4; ++m2) {
                    const double dm  = D[j][m2] - D[j - 1][m2];
                    const double dm1 = (m2 > 0) ? (D[j][m2 - 1] - D[j - 1][m2 - 1]) : 0.0;
                    nf[m2] = D[j - 1][m2] + B * dm + A * dm1;
                }
                for (int m2 = 0; m2 < 4; ++m2) D[j][m2] = nf[m2];
            }
        }
        s_p[s][0] = (float)D[3][0];  s_p[s][1] = (float)D[3][1];
        s_p[s][2] = (float)D[3][2];  s_p[s][3] = (float)D[3][3];
        s_lo[s] = (float)x0;
        g_segPoly[4 * s + 0] = s_p[s][0];
        g_segPoly[4 * s + 1] = s_p[s][1];
        g_segPoly[4 * s + 2] = s_p[s][2];
        g_segPoly[4 * s + 3] = s_p[s][3];
        g_segLo[s] = s_lo[s];
    }
    __syncthreads();

    // Per-bin re-centered cubic. Bin b = [b/4096, (b+1)/4096). Polynomial in
    // v = xc - center(b).  p(u0+v): p'0=p(u0), p'1=p1+2p2u0+3p3u0^2,
    // p'2=p2+3p3u0, p'3=p3.  u0 = center - k[s] in [0, h_s) -> well-conditioned.
    for (int b = t; b < NBIN; b += 256) {
        const float binLo = (float)b * (1.0f / (float)NBIN);
        const float binHi = (float)(b + 1) * (1.0f / (float)NBIN);
        int s = 0;
        bool impure = false;
        #pragma unroll
        for (int i = 1; i < 16; ++i) {
            s += (s_k[i] <= binLo) ? 1 : 0;
            impure |= (s_k[i] > binLo) & (s_k[i] < binHi);
        }
        if (s > NSEG - 1) s = NSEG - 1;

        const float c  = (float)(2 * b + 1) * (1.0f / (2.0f * (float)NBIN));
        const float u0 = c - s_lo[s];
        const float p0 = s_p[s][0], p1 = s_p[s][1], p2 = s_p[s][2], p3 = s_p[s][3];

        float4 q;
        q.x = fmaf(fmaf(fmaf(p3, u0, p2), u0, p1), u0, p0);
        q.y = fmaf(fmaf(3.0f * p3, u0, 2.0f * p2), u0, p1);
        q.z = fmaf(3.0f * p3, u0, p2);
        // impure flag lives in the LSB of p3 (<=1 ulp perturbation)
        unsigned int w3 = __float_as_uint(p3) & ~1u;
        if (impure) w3 |= 1u;
        q.w = __uint_as_float(w3);
        g_binPoly[b] = q;
    }
}

// ---------------------------------------------------------------------------
// Hot loop. 66 KB dynamic shared: 4096 bin cubics + slow-path tables.
// ---------------------------------------------------------------------------
#define SMEM_BINS_BYTES   (NBIN * 16)
#define SMEM_SEGP_OFF     SMEM_BINS_BYTES                 // 15 * float4
#define SMEM_SEGLO_OFF    (SMEM_SEGP_OFF + NSEG * 16)     // 16 * float
#define SMEM_KNOTS_OFF    (SMEM_SEGLO_OFF + 16 * 4)       // 16 * float
#define SMEM_EVAL_TOTAL   (SMEM_KNOTS_OFF + 16 * 4)

__device__ __forceinline__ float eval_one(float xi,
                                          const float4* __restrict__ sBins,
                                          const float4* __restrict__ sSegP,
                                          const float*  __restrict__ sSegLo,
                                          const float*  __restrict__ sKnots)
{
    const float INV_SQRT3 = 0.5773502691896258f;
    const float xc = fminf(fmaxf(xi * INV_SQRT3, 0.0f), 0.99990000f);
    const int b = (int)(xc * (float)NBIN);
    const float4 p = sBins[b];
    if (__float_as_uint(p.w) & 1u) {            // rare: bin contains a knot
        int s = 0;
        #pragma unroll
        for (int i = 1; i < 16; ++i) s += (sKnots[i] <= xc) ? 1 : 0;
        if (s > NSEG - 1) s = NSEG - 1;
        const float4 q = sSegP[s];
        const float u = xc - sSegLo[s];
        return fmaf(fmaf(fmaf(q.w, u, q.z), u, q.y), u, q.x);
    }
    // v = xc - center(b): exact (power-of-2 scale + Sterbenz subtraction)
    const float v = fmaf((float)b, -1.0f / (float)NBIN, xc) - (0.5f / (float)NBIN);
    return fmaf(fmaf(fmaf(p.w, v, p.z), v, p.y), v, p.x);
}

__global__ void __launch_bounds__(256)
eval_kernel(const float4* __restrict__ x4, float4* __restrict__ o4, int n4)
{
    extern __shared__ __align__(16) unsigned char smem[];
    float4* sBins  = reinterpret_cast<float4*>(smem);
    float4* sSegP  = reinterpret_cast<float4*>(smem + SMEM_SEGP_OFF);
    float*  sSegLo = reinterpret_cast<float*>(smem + SMEM_SEGLO_OFF);
    float*  sKnots = reinterpret_cast<float*>(smem + SMEM_KNOTS_OFF);

    const int tid = threadIdx.x;
    #pragma unroll
    for (int i = 0; i < NBIN / 256; ++i)
        sBins[tid + i * 256] = g_binPoly[tid + i * 256];
    if (tid < NSEG) {
        sSegP[tid]  = reinterpret_cast<const float4*>(g_segPoly)[tid];
        sSegLo[tid] = g_segLo[tid];
    }
    if (tid < 16) sKnots[tid] = g_knots[tid];
    __syncthreads();

    const int stride = gridDim.x * blockDim.x;
    int i = blockIdx.x * blockDim.x + tid;

    // unroll-4: front-batched independent loads for MLP
    for (; i + 3 * stride < n4; i += 4 * stride) {
        const float4 a0 = x4[i];
        const float4 a1 = x4[i + stride];
        const float4 a2 = x4[i + 2 * stride];
        const float4 a3 = x4[i + 3 * stride];
        float4 r0, r1, r2, r3;
        r0.x = eval_one(a0.x, sBins, sSegP, sSegLo, sKnots);
        r0.y = eval_one(a0.y, sBins, sSegP, sSegLo, sKnots);
        r0.z = eval_one(a0.z, sBins, sSegP, sSegLo, sKnots);
        r0.w = eval_one(a0.w, sBins, sSegP, sSegLo, sKnots);
        r1.x = eval_one(a1.x, sBins, sSegP, sSegLo, sKnots);
        r1.y = eval_one(a1.y, sBins, sSegP, sSegLo, sKnots);
        r1.z = eval_one(a1.z, sBins, sSegP, sSegLo, sKnots);
        r1.w = eval_one(a1.w, sBins, sSegP, sSegLo, sKnots);
        r2.x = eval_one(a2.x, sBins, sSegP, sSegLo, sKnots);
        r2.y = eval_one(a2.y, sBins, sSegP, sSegLo, sKnots);
        r2.z = eval_one(a2.z, sBins, sSegP, sSegLo, sKnots);
        r2.w = eval_one(a2.w, sBins, sSegP, sSegLo, sKnots);
        r3.x = eval_one(a3.x, sBins, sSegP, sSegLo, sKnots);
        r3.y = eval_one(a3.y, sBins, sSegP, sSegLo, sKnots);
        r3.z = eval_one(a3.z, sBins, sSegP, sSegLo, sKnots);
        r3.w = eval_one(a3.w, sBins, sSegP, sSegLo, sKnots);
        o4[i]              = r0;
        o4[i + stride]     = r1;
        o4[i + 2 * stride] = r2;
        o4[i + 3 * stride] = r3;
    }
    for (; i < n4; i += stride) {
        const float4 a = x4[i];
        float4 r;
        r.x = eval_one(a.x, sBins, sSegP, sSegLo, sKnots);
        r.y = eval_one(a.y, sBins, sSegP, sSegLo, sKnots);
        r.z = eval_one(a.z, sBins, sSegP, sSegLo, sKnots);
        r.w = eval_one(a.w, sBins, sSegP, sSegLo, sKnots);
        o4[i] = r;
    }
}

// Scalar fallback (tail elements / unexpected misalignment). Reads bin table
// through L1; rare path so simplicity wins.
__global__ void __launch_bounds__(256)
eval_kernel_scalar(const float* __restrict__ x, float* __restrict__ out,
                   int start, int n)
{
    __shared__ __align__(16) float4 sSegP[NSEG + 1];
    __shared__ float sSegLo[16], sKnots[16];
    const int tid = threadIdx.x;
    if (tid < NSEG) {
        sSegP[tid]  = reinterpret_cast<const float4*>(g_segPoly)[tid];
        sSegLo[tid] = g_segLo[tid];
    }
    if (tid < 16) sKnots[tid] = g_knots[tid];
    __syncthreads();

    const int stride = gridDim.x * blockDim.x;
    for (int j = start + blockIdx.x * blockDim.x + tid; j < n; j += stride) {
        const float INV_SQRT3 = 0.5773502691896258f;
        const float xc = fminf(fmaxf(x[j] * INV_SQRT3, 0.0f), 0.99990000f);
        const int b = (int)(xc * (float)NBIN);
        const float4 p = g_binPoly[b];
        float r;
        if (__float_as_uint(p.w) & 1u) {
            int s = 0;
            #pragma unroll
            for (int i = 1; i < 16; ++i) s += (sKnots[i] <= xc) ? 1 : 0;
            if (s > NSEG - 1) s = NSEG - 1;
            const float4 q = sSegP[s];
            const float u = xc - sSegLo[s];
            r = fmaf(fmaf(fmaf(q.w, u, q.z), u, q.y), u, q.x);
        } else {
            const float v = fmaf((float)b, -1.0f / (float)NBIN, xc) - (0.5f / (float)NBIN);
            r = fmaf(fmaf(fmaf(p.w, v, p.z), v, p.y), v, p.x);
        }
        out[j] = r;
    }
}

// ---------------------------------------------------------------------------
extern "C" void kernel_launch(void* const* d_in, const int* in_sizes, int n_in,
                              void* d_out, int out_size)
{
    const float* x  = (const float*)d_in[0];
    const float* a  = (const float*)d_in[1];
    const float* W1 = (const float*)d_in[2];
    const float* b1 = (const float*)d_in[3];
    const float* W2 = (const float*)d_in[4];
    const float* b2 = (const float*)d_in[5];
    const float* Ww = (const float*)d_in[6];
    const float* bw = (const float*)d_in[7];
    const float* Wk = (const float*)d_in[8];
    const float* bk = (const float*)d_in[9];
    float* out = (float*)d_out;
    const int n = in_sizes[0];

    cudaFuncSetAttribute(eval_kernel,
                         cudaFuncAttributeMaxDynamicSharedMemorySize,
                         SMEM_EVAL_TOTAL);

    setup_kernel<<<1, 256>>>(a, W1, b1, W2, b2, Ww, bw, Wk, bk);

    const bool aligned16 = ((((uintptr_t)x) | ((uintptr_t)out)) & 0xF) == 0;
    if (aligned16) {
        const int n4 = n >> 2;
        if (n4 > 0) {
            int blocks = 148 * 3;            // 3 blocks/SM (66 KB smem each)
            const int maxBlocks = (n4 + 255) / 256;
            if (blocks > maxBlocks) blocks = maxBlocks;
            eval_kernel<<<blocks, 256, SMEM_EVAL_TOTAL>>>(
                reinterpret_cast<const float4*>(x),
                reinterpret_cast<float4*>(out), n4);
        }
        if ((n4 << 2) < n)
            eval_kernel_scalar<<<1, 256>>>(x, out, n4 << 2, n);
    } else {
        int blocks = (n + 255) / 256;
        if (blocks > 1536) blocks = 1536;
        eval_kernel_scalar<<<blocks, 256>>>(x, out, 0, n);
    }
}

// round 9
// speedup vs baseline: 1.4192x; 1.4192x over previous
#include <cuda_runtime.h>
#include <cstdint>

// ---------------------------------------------------------------------------
// NeuralSplineFourierFilter: tiny MLP on scalar 'a' -> 16 knots + 18 control
// points -> degree-3 B-spline on a 256^3 grid.
//
// R7: the spline is C^2, tolerance is 1e-3 -> piecewise-LINEAR table of 4096
// bins is accurate to ~1e-5. Hot loop: clamp-scale, LDS.64 of (f_lo, f_hi),
// one lerp. 8 B gather/point instead of 16 B (R6's LDS.128 saturated the
// smem crossbar at 78% L1 while DRAM idled at 25%). No slow path at all.
// ---------------------------------------------------------------------------

#define NBIN  4096
#define NEDGE (NBIN + 1)

// (f(b/NBIN), f((b+1)/NBIN)) per bin. 32 KB. __align__(16) so the eval
// kernel can stage it into shared with float4 copies.
__device__ __align__(16) float2 g_bins[NBIN];

// ---------------------------------------------------------------------------
// Fused setup: MLP + softmax/cumsum knots + numeric fp32 de Boor at the
// 4097 bin edges. 1 block, 256 threads.
// ---------------------------------------------------------------------------
__global__ void __launch_bounds__(256)
setup_kernel(const float* __restrict__ a_in,
             const float* __restrict__ W1, const float* __restrict__ b1,
             const float* __restrict__ W2, const float* __restrict__ b2,
             const float* __restrict__ Ww, const float* __restrict__ bw,
             const float* __restrict__ Wk, const float* __restrict__ bk)
{
    __shared__ float s_net[32], s_net2[32], s_klog[15];
    __shared__ float s_k[16];          // knots, k[0] = 0
    __shared__ float s_c[18];          // control points, c[0] = 0
    __shared__ float s_T[22];          // padded knot vector
    __shared__ float s_edge[NEDGE];    // f at bin edges (16.4 KB)
    const int t = threadIdx.x;

    if (t < 32) {
        const float a = a_in[0];
        s_net[t] = sinf(fmaf(a, W1[t], b1[t]));
    }
    __syncthreads();
    if (t < 32) {
        float acc = b2[t];
        #pragma unroll
        for (int j = 0; j < 32; ++j) acc = fmaf(s_net[j], W2[j * 32 + t], acc);
        s_net2[t] = sinf(acc);
    }
    __syncthreads();
    if (t < 17) {                      // control-point deltas -> s_c[1..17]
        float w = bw[t];
        #pragma unroll
        for (int j = 0; j < 32; ++j) w = fmaf(s_net2[j], Ww[j * 17 + t], w);
        s_c[t + 1] = w;
    }
    if (t >= 32 && t < 47) {           // knot logits (runs alongside w rows)
        const int i = t - 32;
        float kk = bk[i];
        #pragma unroll
        for (int j = 0; j < 32; ++j) kk = fmaf(s_net2[j], Wk[j * 15 + i], kk);
        s_klog[i] = kk;
    }
    __syncthreads();
    if (t == 0) {
        float m = s_klog[0];
        for (int i = 1; i < 15; ++i) m = fmaxf(m, s_klog[i]);
        float e[15], sum = 0.f;
        for (int i = 0; i < 15; ++i) { e[i] = expf(s_klog[i] - m); sum += e[i]; }
        const float inv = 1.0f / sum;
        float cs = 0.f;
        s_k[0] = 0.f;
        for (int i = 0; i < 15; ++i) { cs += e[i] * inv; s_k[i + 1] = cs; }
        s_c[0] = 0.f;
    }
    __syncthreads();
    if (t < 3)              s_T[t]      = 0.f;
    if (t < 16)             s_T[3 + t]  = s_k[t];
    if (t >= 19 && t < 22)  s_T[t]      = 1.f;
    __syncthreads();

    // Numeric de Boor (mirrors the reference) at every bin edge, fp32.
    for (int e = t; e < NEDGE; e += 256) {
        const float xe = (float)e * (1.0f / (float)NBIN);  // exact (pow2)
        int s = 0;
        #pragma unroll
        for (int i = 1; i < 16; ++i) s += (s_k[i] <= xe) ? 1 : 0;
        if (s > 14) s = 14;
        // kidx = s + 3; c gathers are c[s .. s+3]
        float d0 = s_c[s], d1 = s_c[s + 1], d2 = s_c[s + 2], d3 = s_c[s + 3];
        #pragma unroll
        for (int r = 1; r <= 3; ++r) {
            #pragma unroll
            for (int j = 3; j >= 1; --j) {
                if (j < r) continue;
                const float tlo = s_T[j + s];
                const float thi = s_T[j + 1 + s + 3 - r];
                const float alpha = (xe - tlo) / (thi - tlo);
                const float dl = (j == 1) ? d0 : ((j == 2) ? d1 : d2);
                const float dj = (j == 1) ? d1 : ((j == 2) ? d2 : d3);
                const float nd = fmaf(alpha, dj - dl, dl);
                if (j == 1) d1 = nd; else if (j == 2) d2 = nd; else d3 = nd;
            }
        }
        s_edge[e] = d3;
    }
    __syncthreads();

    for (int b = t; b < NBIN; b += 256)
        g_bins[b] = make_float2(s_edge[b], s_edge[b + 1]);
}

// ---------------------------------------------------------------------------
// Hot loop. 32 KB shared bin table, one LDS.64 + lerp per point.
// ---------------------------------------------------------------------------
#define KSCALE  (4096.0f * 0.5773502691896258f)   // NBIN / sqrt(3)
#define TMAX    ((1.0f - 1e-4f) * 4096.0f)        // clip bound, scaled

__device__ __forceinline__ float eval_one(float xi, const float2* __restrict__ sBins)
{
    const float tt = fminf(fmaxf(xi * KSCALE, 0.0f), TMAX);
    const int   b  = (int)tt;
    const float fr = tt - (float)b;
    const float2 v = sBins[b];
    return fmaf(fr, v.y - v.x, v.x);
}

__global__ void __launch_bounds__(256)
eval_kernel(const float4* __restrict__ x4, float4* __restrict__ o4, int n4)
{
    extern __shared__ __align__(16) unsigned char smem[];
    float2* sBins = reinterpret_cast<float2*>(smem);

    const int tid = threadIdx.x;
    {   // 32 KB table: 2048 float4 copies, 8 per thread
        float4* dst = reinterpret_cast<float4*>(smem);
        const float4* src = reinterpret_cast<const float4*>(g_bins);
        #pragma unroll
        for (int i = 0; i < NBIN / 2 / 256; ++i)
            dst[tid + i * 256] = src[tid + i * 256];
    }
    __syncthreads();

    const int stride = gridDim.x * blockDim.x;
    int i = blockIdx.x * blockDim.x + tid;

    for (; i + 3 * stride < n4; i += 4 * stride) {
        const float4 a0 = x4[i];
        const float4 a1 = x4[i + stride];
        const float4 a2 = x4[i + 2 * stride];
        const float4 a3 = x4[i + 3 * stride];
        float4 r0, r1, r2, r3;
        r0.x = eval_one(a0.x, sBins); r0.y = eval_one(a0.y, sBins);
        r0.z = eval_one(a0.z, sBins); r0.w = eval_one(a0.w, sBins);
        r1.x = eval_one(a1.x, sBins); r1.y = eval_one(a1.y, sBins);
        r1.z = eval_one(a1.z, sBins); r1.w = eval_one(a1.w, sBins);
        r2.x = eval_one(a2.x, sBins); r2.y = eval_one(a2.y, sBins);
        r2.z = eval_one(a2.z, sBins); r2.w = eval_one(a2.w, sBins);
        r3.x = eval_one(a3.x, sBins); r3.y = eval_one(a3.y, sBins);
        r3.z = eval_one(a3.z, sBins); r3.w = eval_one(a3.w, sBins);
        o4[i]              = r0;
        o4[i + stride]     = r1;
        o4[i + 2 * stride] = r2;
        o4[i + 3 * stride] = r3;
    }
    for (; i < n4; i += stride) {
        const float4 a = x4[i];
        float4 r;
        r.x = eval_one(a.x, sBins); r.y = eval_one(a.y, sBins);
        r.z = eval_one(a.z, sBins); r.w = eval_one(a.w, sBins);
        o4[i] = r;
    }
}

// Scalar fallback (tail / unexpected misalignment): reads the bin table
// through L1 directly. Rare path.
__global__ void __launch_bounds__(256)
eval_kernel_scalar(const float* __restrict__ x, float* __restrict__ out,
                   int start, int n)
{
    const int stride = gridDim.x * blockDim.x;
    for (int j = start + blockIdx.x * blockDim.x + threadIdx.x; j < n; j += stride) {
        const float tt = fminf(fmaxf(x[j] * KSCALE, 0.0f), TMAX);
        const int   b  = (int)tt;
        const float fr = tt - (float)b;
        const float2 v = g_bins[b];
        out[j] = fmaf(fr, v.y - v.x, v.x);
    }
}

// ---------------------------------------------------------------------------
extern "C" void kernel_launch(void* const* d_in, const int* in_sizes, int n_in,
                              void* d_out, int out_size)
{
    const float* x  = (const float*)d_in[0];
    const float* a  = (const float*)d_in[1];
    const float* W1 = (const float*)d_in[2];
    const float* b1 = (const float*)d_in[3];
    const float* W2 = (const float*)d_in[4];
    const float* b2 = (const float*)d_in[5];
    const float* Ww = (const float*)d_in[6];
    const float* bw = (const float*)d_in[7];
    const float* Wk = (const float*)d_in[8];
    const float* bk = (const float*)d_in[9];
    float* out = (float*)d_out;
    const int n = in_sizes[0];

    const int SMEM_EVAL = NBIN * (int)sizeof(float2);   // 32 KB
    cudaFuncSetAttribute(eval_kernel,
                         cudaFuncAttributeMaxDynamicSharedMemorySize, SMEM_EVAL);

    setup_kernel<<<1, 256>>>(a, W1, b1, W2, b2, Ww, bw, Wk, bk);

    const bool aligned16 = ((((uintptr_t)x) | ((uintptr_t)out)) & 0xF) == 0;
    if (aligned16) {
        const int n4 = n >> 2;
        if (n4 > 0) {
            int blocks = 148 * 6;                       // ~6 blocks/SM resident
            const int maxBlocks = (n4 + 255) / 256;
            if (blocks > maxBlocks) blocks = maxBlocks;
            eval_kernel<<<blocks, 256, SMEM_EVAL>>>(
                reinterpret_cast<const float4*>(x),
                reinterpret_cast<float4*>(out), n4);
        }
        if ((n4 << 2) < n)
            eval_kernel_scalar<<<1, 256>>>(x, out, n4 << 2, n);
    } else {
        int blocks = (n + 255) / 256;
        if (blocks > 1536) blocks = 1536;
        eval_kernel_scalar<<<blocks, 256>>>(x, out, 0, n);
    }
}

// round 11
// speedup vs baseline: 1.5942x; 1.1233x over previous
#include <cuda_runtime.h>
#include <cstdint>

// ---------------------------------------------------------------------------
// NeuralSplineFourierFilter: tiny MLP on scalar 'a' -> 16 knots + 18 control
// points -> degree-3 B-spline on a 256^3 grid.
//
// R8: setup shrinks to 15 symbolic fp64 segment cubics (no per-edge MUFU
// storm — R7's 4097-edge division loop on one SM cost ~16 us). Each eval
// block rebuilds its 2048-bin linear table in shared from the cubics with
// pure FMA. Hot loop unchanged: clamp-scale, LDS.64 (f_lo, f_hi), lerp.
// 16 KB table -> 8 blocks/SM (full 2048-thread occupancy).
// ---------------------------------------------------------------------------

#define NSEG 15
#define NBIN 2048

__device__ __align__(16) float g_segPoly[NSEG * 4]; // cubic in u = x - k[s]
__device__ __align__(16) float g_segLo[NSEG + 1];
__device__ __align__(16) float g_knots[16];

// ---------------------------------------------------------------------------
// Kernel A: MLP + softmax/cumsum + symbolic fp64 de Boor. 1 block, 64 thr.
// ---------------------------------------------------------------------------
__global__ void __launch_bounds__(64)
setup_kernel(const float* __restrict__ a_in,
             const float* __restrict__ W1, const float* __restrict__ b1,
             const float* __restrict__ W2, const float* __restrict__ b2,
             const float* __restrict__ Ww, const float* __restrict__ bw,
             const float* __restrict__ Wk, const float* __restrict__ bk)
{
    __shared__ float s_net[32], s_net2[32], s_klog[15];
    __shared__ float s_k[16], s_c[18];
    const int t = threadIdx.x;

    if (t < 32) {
        const float a = a_in[0];
        s_net[t] = sinf(fmaf(a, W1[t], b1[t]));
    }
    __syncthreads();
    if (t < 32) {
        float acc = b2[t];
        #pragma unroll
        for (int j = 0; j < 32; ++j) acc = fmaf(s_net[j], W2[j * 32 + t], acc);
        s_net2[t] = sinf(acc);
    }
    __syncthreads();
    if (t < 17) {                       // control-point deltas -> s_c[1..17]
        float w = bw[t];
        #pragma unroll
        for (int j = 0; j < 32; ++j) w = fmaf(s_net2[j], Ww[j * 17 + t], w);
        s_c[t + 1] = w;
    }
    if (t >= 32 && t < 47) {            // knot logits, overlapped
        const int i = t - 32;
        float kk = bk[i];
        #pragma unroll
        for (int j = 0; j < 32; ++j) kk = fmaf(s_net2[j], Wk[j * 15 + i], kk);
        s_klog[i] = kk;
    }
    __syncthreads();
    if (t == 0) {
        float m = s_klog[0];
        for (int i = 1; i < 15; ++i) m = fmaxf(m, s_klog[i]);
        float e[15], sum = 0.f;
        for (int i = 0; i < 15; ++i) { e[i] = expf(s_klog[i] - m); sum += e[i]; }
        const float inv = 1.0f / sum;
        float cs = 0.f;
        s_k[0] = 0.f;
        for (int i = 0; i < 15; ++i) { cs += e[i] * inv; s_k[i + 1] = cs; }
        s_c[0] = 0.f;
    }
    __syncthreads();

    if (t < 16) g_knots[t] = s_k[t];

    // Symbolic de Boor: exact cubic per segment in u = x - k[s]. fp64,
    // 15 threads, ~6 divisions each — negligible.
    if (t < NSEG) {
        double T[22];
        for (int i = 0; i < 3; ++i)  T[i] = 0.0;
        for (int i = 0; i < 16; ++i) T[3 + i] = (double)s_k[i];
        for (int i = 19; i < 22; ++i) T[i] = 1.0;

        const int s = t;
        const double x0 = T[s + 3];

        double D[4][4];
        for (int j = 0; j < 4; ++j) {
            D[j][0] = (double)s_c[s + j];
            D[j][1] = D[j][2] = D[j][3] = 0.0;
        }
        for (int r = 1; r <= 3; ++r) {
            for (int j = 3; j >= r; --j) {
                const double tlo = T[j + s];
                const double thi = T[j + 1 + s + 3 - r];
                const double A = 1.0 / (thi - tlo);
                const double B = A * (x0 - tlo);     // alpha(u) = A*u + B
                double nf[4];
                for (int m2 = 0; m2 < 4; ++m2) {
                    const double dm  = D[j][m2] - D[j - 1][m2];
                    const double dm1 = (m2 > 0) ? (D[j][m2 - 1] - D[j - 1][m2 - 1]) : 0.0;
                    nf[m2] = D[j - 1][m2] + B * dm + A * dm1;
                }
                for (int m2 = 0; m2 < 4; ++m2) D[j][m2] = nf[m2];
            }
        }
        g_segPoly[4 * s + 0] = (float)D[3][0];
        g_segPoly[4 * s + 1] = (float)D[3][1];
        g_segPoly[4 * s + 2] = (float)D[3][2];
        g_segPoly[4 * s + 3] = (float)D[3][3];
        g_segLo[s] = (float)x0;
    }
}

// ---------------------------------------------------------------------------
// Eval: build 2048-bin linear table in shared (FMA only), then lerp loop.
// ---------------------------------------------------------------------------
#define KSCALE ((float)NBIN * 0.5773502691896258f)   // NBIN / sqrt(3)
#define TMAX   ((1.0f - 1e-4f) * (float)NBIN)

#define SMEM_BINS_BYTES (NBIN * 8)
#define SMEM_SEGP_OFF   SMEM_BINS_BYTES
#define SMEM_SEGLO_OFF  (SMEM_SEGP_OFF + NSEG * 16)
#define SMEM_KNOTS_OFF  (SMEM_SEGLO_OFF + 16 * 4)
#define SMEM_EVAL_TOTAL (SMEM_KNOTS_OFF + 16 * 4)

__device__ __forceinline__ float spline_at(float xe,
                                           const float4* __restrict__ sSegP,
                                           const float*  __restrict__ sSegLo,
                                           const float*  __restrict__ sKnots)
{
    int s = 0;
    #pragma unroll
    for (int i = 1; i < 16; ++i) s += (sKnots[i] <= xe) ? 1 : 0;
    if (s > NSEG - 1) s = NSEG - 1;
    const float4 q = sSegP[s];
    const float u = xe - sSegLo[s];
    return fmaf(fmaf(fmaf(q.w, u, q.z), u, q.y), u, q.x);
}

__device__ __forceinline__ float eval_one(float xi, const float2* __restrict__ sBins)
{
    const float tt = fminf(fmaxf(xi * KSCALE, 0.0f), TMAX);
    const int   b  = (int)tt;
    const float fr = tt - (float)b;
    const float2 v = sBins[b];
    return fmaf(fr, v.y - v.x, v.x);
}

__global__ void __launch_bounds__(256)
eval_kernel(const float4* __restrict__ x4, float4* __restrict__ o4, int n4)
{
    extern __shared__ __align__(16) unsigned char smem[];
    float2* sBins  = reinterpret_cast<float2*>(smem);
    float4* sSegP  = reinterpret_cast<float4*>(smem + SMEM_SEGP_OFF);
    float*  sSegLo = reinterpret_cast<float*>(smem + SMEM_SEGLO_OFF);
    float*  sKnots = reinterpret_cast<float*>(smem + SMEM_KNOTS_OFF);

    const int tid = threadIdx.x;
    if (tid < NSEG) {
        sSegP[tid]  = reinterpret_cast<const float4*>(g_segPoly)[tid];
        sSegLo[tid] = g_segLo[tid];
    }
    if (tid < 16) sKnots[tid] = g_knots[tid];
    __syncthreads();

    // Build the bin table: each thread fills NBIN/256 = 8 bins. Both edges
    // evaluated per bin (adjacent bins recompute identically -> continuous).
    #pragma unroll
    for (int i = 0; i < NBIN / 256; ++i) {
        const int b = tid + i * 256;
        const float xe0 = (float)b       * (1.0f / (float)NBIN);  // exact
        const float xe1 = (float)(b + 1) * (1.0f / (float)NBIN);
        sBins[b] = make_float2(spline_at(xe0, sSegP, sSegLo, sKnots),
                               spline_at(xe1, sSegP, sSegLo, sKnots));
    }
    __syncthreads();

    const int stride = gridDim.x * blockDim.x;
    int i = blockIdx.x * blockDim.x + tid;

    for (; i + 3 * stride < n4; i += 4 * stride) {
        const float4 a0 = x4[i];
        const float4 a1 = x4[i + stride];
        const float4 a2 = x4[i + 2 * stride];
        const float4 a3 = x4[i + 3 * stride];
        float4 r0, r1, r2, r3;
        r0.x = eval_one(a0.x, sBins); r0.y = eval_one(a0.y, sBins);
        r0.z = eval_one(a0.z, sBins); r0.w = eval_one(a0.w, sBins);
        r1.x = eval_one(a1.x, sBins); r1.y = eval_one(a1.y, sBins);
        r1.z = eval_one(a1.z, sBins); r1.w = eval_one(a1.w, sBins);
        r2.x = eval_one(a2.x, sBins); r2.y = eval_one(a2.y, sBins);
        r2.z = eval_one(a2.z, sBins); r2.w = eval_one(a2.w, sBins);
        r3.x = eval_one(a3.x, sBins); r3.y = eval_one(a3.y, sBins);
        r3.z = eval_one(a3.z, sBins); r3.w = eval_one(a3.w, sBins);
        o4[i]              = r0;
        o4[i + stride]     = r1;
        o4[i + 2 * stride] = r2;
        o4[i + 3 * stride] = r3;
    }
    for (; i < n4; i += stride) {
        const float4 a = x4[i];
        float4 r;
        r.x = eval_one(a.x, sBins); r.y = eval_one(a.y, sBins);
        r.z = eval_one(a.z, sBins); r.w = eval_one(a.w, sBins);
        o4[i] = r;
    }
}

// Scalar fallback (tail / misalignment): exact segment-cubic per point via
// global tables (L1-cached). Rare path.
__global__ void __launch_bounds__(256)
eval_kernel_scalar(const float* __restrict__ x, float* __restrict__ out,
                   int start, int n)
{
    __shared__ __align__(16) float4 sSegP[NSEG + 1];
    __shared__ float sSegLo[16], sKnots[16];
    const int tid = threadIdx.x;
    if (tid < NSEG) {
        sSegP[tid]  = reinterpret_cast<const float4*>(g_segPoly)[tid];
        sSegLo[tid] = g_segLo[tid];
    }
    if (tid < 16) sKnots[tid] = g_knots[tid];
    __syncthreads();

    const float INV_SQRT3 = 0.5773502691896258f;
    const int stride = gridDim.x * blockDim.x;
    for (int j = start + blockIdx.x * blockDim.x + tid; j < n; j += stride) {
        const float xc = fminf(fmaxf(x[j] * INV_SQRT3, 0.0f), 0.99990000f);
        out[j] = spline_at(xc, sSegP, sSegLo, sKnots);
    }
}

// ---------------------------------------------------------------------------
extern "C" void kernel_launch(void* const* d_in, const int* in_sizes, int n_in,
                              void* d_out, int out_size)
{
    const float* x  = (const float*)d_in[0];
    const float* a  = (const float*)d_in[1];
    const float* W1 = (const float*)d_in[2];
    const float* b1 = (const float*)d_in[3];
    const float* W2 = (const float*)d_in[4];
    const float* b2 = (const float*)d_in[5];
    const float* Ww = (const float*)d_in[6];
    const float* bw = (const float*)d_in[7];
    const float* Wk = (const float*)d_in[8];
    const float* bk = (const float*)d_in[9];
    float* out = (float*)d_out;
    const int n = in_sizes[0];

    cudaFuncSetAttribute(eval_kernel,
                         cudaFuncAttributeMaxDynamicSharedMemorySize,
                         SMEM_EVAL_TOTAL);

    setup_kernel<<<1, 64>>>(a, W1, b1, W2, b2, Ww, bw, Wk, bk);

    const bool aligned16 = ((((uintptr_t)x) | ((uintptr_t)out)) & 0xF) == 0;
    if (aligned16) {
        const int n4 = n >> 2;
        if (n4 > 0) {
            int blocks = 148 * 8;              // 8 blocks/SM (2048-thread cap)
            const int maxBlocks = (n4 + 255) / 256;
            if (blocks > maxBlocks) blocks = maxBlocks;
            eval_kernel<<<blocks, 256, SMEM_EVAL_TOTAL>>>(
                reinterpret_cast<const float4*>(x),
                reinterpret_cast<float4*>(out), n4);
        }
        if ((n4 << 2) < n)
            eval_kernel_scalar<<<1, 256>>>(x, out, n4 << 2, n);
    } else {
        int blocks = (n + 255) / 256;
        if (blocks > 1536) blocks = 1536;
        eval_kernel_scalar<<<blocks, 256>>>(x, out, 0, n);
    }
}

// round 12
// speedup vs baseline: 1.6745x; 1.0504x over previous
#include <cuda_runtime.h>
#include <cstdint>

// ---------------------------------------------------------------------------
// NeuralSplineFourierFilter: tiny MLP on scalar 'a' -> 16 knots + 18 control
// points -> degree-3 B-spline on a 256^3 grid.
//
// R9: ONE kernel. Every block recomputes the tiny setup (MLP + softmax +
// symbolic fp32 de Boor -> 15 segment cubics) in a ~1.5us prelude, builds a
// 2048-bin piecewise-linear table in shared, then runs the lerp hot loop.
// Removes the ~10us serial setup-kernel + launch-gap cost of R8.
// ---------------------------------------------------------------------------

#define NSEG 15
#define NBIN 2048

#define KSCALE ((float)NBIN * 0.5773502691896258f)   // NBIN / sqrt(3)
#define TMAX   ((1.0f - 1e-4f) * (float)NBIN)

struct __align__(16) SmemLayout {
    float2 bins[NBIN];        // 16 KB: (f_lo, f_hi) per bin
    float4 segP[NSEG + 1];    // segment cubics, local coords u = x - k[s]
    float  segLo[16];
    float  knots[16];
    float  net[32];
    float  net2[32];
    float  klog[16];
    float  c[18];
};

__device__ __forceinline__ float spline_at(float xe, const SmemLayout& sm)
{
    int s = 0;
    #pragma unroll
    for (int i = 1; i < 16; ++i) s += (sm.knots[i] <= xe) ? 1 : 0;
    if (s > NSEG - 1) s = NSEG - 1;
    const float4 q = sm.segP[s];
    const float u = xe - sm.segLo[s];
    return fmaf(fmaf(fmaf(q.w, u, q.z), u, q.y), u, q.x);
}

// Per-block prelude: MLP -> knots/control points -> symbolic de Boor ->
// 2048-bin linear table. All fp32; every block computes identical tables.
__device__ __forceinline__ void build_tables(
    SmemLayout& sm, int t, int nthreads,
    const float* __restrict__ a_in,
    const float* __restrict__ W1, const float* __restrict__ b1,
    const float* __restrict__ W2, const float* __restrict__ b2,
    const float* __restrict__ Ww, const float* __restrict__ bw,
    const float* __restrict__ Wk, const float* __restrict__ bk)
{
    if (t < 32) {
        const float a = a_in[0];
        sm.net[t] = sinf(fmaf(a, W1[t], b1[t]));
    }
    __syncthreads();
    if (t < 32) {
        float acc = b2[t];
        #pragma unroll
        for (int j = 0; j < 32; ++j) acc = fmaf(sm.net[j], W2[j * 32 + t], acc);
        sm.net2[t] = sinf(acc);
    }
    __syncthreads();
    if (t < 17) {                       // control-point deltas -> c[1..17]
        float w = bw[t];
        #pragma unroll
        for (int j = 0; j < 32; ++j) w = fmaf(sm.net2[j], Ww[j * 17 + t], w);
        sm.c[t + 1] = w;
    }
    if (t >= 32 && t < 47) {            // knot logits, overlapped warp
        const int i = t - 32;
        float kk = bk[i];
        #pragma unroll
        for (int j = 0; j < 32; ++j) kk = fmaf(sm.net2[j], Wk[j * 15 + i], kk);
        sm.klog[i] = kk;
    }
    __syncthreads();
    if (t == 0) {                       // softmax + cumsum -> monotone knots
        float m = sm.klog[0];
        for (int i = 1; i < 15; ++i) m = fmaxf(m, sm.klog[i]);
        float e[15], sum = 0.f;
        for (int i = 0; i < 15; ++i) { e[i] = expf(sm.klog[i] - m); sum += e[i]; }
        const float inv = 1.0f / sum;
        float cs = 0.f;
        sm.knots[0] = 0.f;
        for (int i = 0; i < 15; ++i) { cs += e[i] * inv; sm.knots[i + 1] = cs; }
        sm.c[0] = 0.f;
    }
    __syncthreads();

    // Symbolic de Boor (fp32): exact cubic per segment in u = x - k[s].
    // Local coords keep every Horner term O(|c|): no catastrophic
    // cancellation, fp32 coefficient error ~1e-6 << 1.7e-5 table error.
    if (t < NSEG) {
        float T[22];
        #pragma unroll
        for (int i = 0; i < 3; ++i)  T[i] = 0.f;
        #pragma unroll
        for (int i = 0; i < 16; ++i) T[3 + i] = sm.knots[i];
        #pragma unroll
        for (int i = 19; i < 22; ++i) T[i] = 1.f;

        const int s = t;
        const float x0 = T[s + 3];

        float D[4][4];
        #pragma unroll
        for (int j = 0; j < 4; ++j) {
            D[j][0] = sm.c[s + j];
            D[j][1] = D[j][2] = D[j][3] = 0.f;
        }
        #pragma unroll
        for (int r = 1; r <= 3; ++r) {
            #pragma unroll
            for (int j = 3; j >= 1; --j) {
                if (j < r) continue;
                const float tlo = T[j + s];
                const float thi = T[j + 1 + s + 3 - r];
                const float A = 1.0f / (thi - tlo);
                const float B = A * (x0 - tlo);      // alpha(u) = A*u + B
                float nf[4];
                #pragma unroll
                for (int m2 = 0; m2 < 4; ++m2) {
                    const float dm  = D[j][m2] - D[j - 1][m2];
                    const float dm1 = (m2 > 0) ? (D[j][m2 - 1] - D[j - 1][m2 - 1]) : 0.f;
                    nf[m2] = fmaf(B, dm, fmaf(A, dm1, D[j - 1][m2]));
                }
                #pragma unroll
                for (int m2 = 0; m2 < 4; ++m2) D[j][m2] = nf[m2];
            }
        }
        sm.segP[s]  = make_float4(D[3][0], D[3][1], D[3][2], D[3][3]);
        sm.segLo[s] = x0;
    }
    __syncthreads();

    // Bin table: both edges evaluated per bin (identical recompute across
    // adjacent bins -> continuous table).
    for (int b = t; b < NBIN; b += nthreads) {
        const float xe0 = (float)b       * (1.0f / (float)NBIN);  // exact
        const float xe1 = (float)(b + 1) * (1.0f / (float)NBIN);
        sm.bins[b] = make_float2(spline_at(xe0, sm), spline_at(xe1, sm));
    }
    __syncthreads();
}

__device__ __forceinline__ float eval_one(float xi, const float2* __restrict__ sBins)
{
    const float tt = fminf(fmaxf(xi * KSCALE, 0.0f), TMAX);
    const int   b  = (int)tt;
    const float fr = tt - (float)b;
    const float2 v = sBins[b];
    return fmaf(fr, v.y - v.x, v.x);
}

__global__ void __launch_bounds__(256)
fused_kernel(const float* __restrict__ x, float* __restrict__ out, int n,
             int vec_ok,
             const float* __restrict__ a_in,
             const float* __restrict__ W1, const float* __restrict__ b1,
             const float* __restrict__ W2, const float* __restrict__ b2,
             const float* __restrict__ Ww, const float* __restrict__ bw,
             const float* __restrict__ Wk, const float* __restrict__ bk)
{
    __shared__ SmemLayout sm;
    const int tid = threadIdx.x;
    build_tables(sm, tid, 256, a_in, W1, b1, W2, b2, Ww, bw, Wk, bk);
    const float2* sBins = sm.bins;

    const int stride = gridDim.x * blockDim.x;

    if (vec_ok) {
        const int n4 = n >> 2;
        const float4* __restrict__ x4 = reinterpret_cast<const float4*>(x);
        float4* __restrict__ o4 = reinterpret_cast<float4*>(out);

        int i = blockIdx.x * blockDim.x + tid;
        for (; i + 3 * stride < n4; i += 4 * stride) {
            const float4 a0 = x4[i];
            const float4 a1 = x4[i + stride];
            const float4 a2 = x4[i + 2 * stride];
            const float4 a3 = x4[i + 3 * stride];
            float4 r0, r1, r2, r3;
            r0.x = eval_one(a0.x, sBins); r0.y = eval_one(a0.y, sBins);
            r0.z = eval_one(a0.z, sBins); r0.w = eval_one(a0.w, sBins);
            r1.x = eval_one(a1.x, sBins); r1.y = eval_one(a1.y, sBins);
            r1.z = eval_one(a1.z, sBins); r1.w = eval_one(a1.w, sBins);
            r2.x = eval_one(a2.x, sBins); r2.y = eval_one(a2.y, sBins);
            r2.z = eval_one(a2.z, sBins); r2.w = eval_one(a2.w, sBins);
            r3.x = eval_one(a3.x, sBins); r3.y = eval_one(a3.y, sBins);
            r3.z = eval_one(a3.z, sBins); r3.w = eval_one(a3.w, sBins);
            o4[i]              = r0;
            o4[i + stride]     = r1;
            o4[i + 2 * stride] = r2;
            o4[i + 3 * stride] = r3;
        }
        for (; i < n4; i += stride) {
            const float4 a = x4[i];
            float4 r;
            r.x = eval_one(a.x, sBins); r.y = eval_one(a.y, sBins);
            r.z = eval_one(a.z, sBins); r.w = eval_one(a.w, sBins);
            o4[i] = r;
        }
        // scalar tail (n % 4 != 0) — exact segment cubic, negligible count
        const float INV_SQRT3 = 0.5773502691896258f;
        for (int j = (n4 << 2) + blockIdx.x * blockDim.x + tid; j < n; j += stride) {
            const float xc = fminf(fmaxf(x[j] * INV_SQRT3, 0.0f), 0.99990000f);
            out[j] = spline_at(xc, sm);
        }
    } else {
        // misalignment fallback: all-scalar lerp loop
        for (int j = blockIdx.x * blockDim.x + tid; j < n; j += stride)
            out[j] = eval_one(x[j], sBins);
    }
}

// ---------------------------------------------------------------------------
extern "C" void kernel_launch(void* const* d_in, const int* in_sizes, int n_in,
                              void* d_out, int out_size)
{
    const float* x  = (const float*)d_in[0];
    const float* a  = (const float*)d_in[1];
    const float* W1 = (const float*)d_in[2];
    const float* b1 = (const float*)d_in[3];
    const float* W2 = (const float*)d_in[4];
    const float* b2 = (const float*)d_in[5];
    const float* Ww = (const float*)d_in[6];
    const float* bw = (const float*)d_in[7];
    const float* Wk = (const float*)d_in[8];
    const float* bk = (const float*)d_in[9];
    float* out = (float*)d_out;
    const int n = in_sizes[0];

    const int vec_ok =
        (((((uintptr_t)x) | ((uintptr_t)out)) & 0xF) == 0) ? 1 : 0;

    int blocks = 148 * 8;                       // exactly one resident wave
    const int work_items = vec_ok ? (n + 3) / 4 : n;
    const int maxBlocks = (work_items + 255) / 256;
    if (blocks > maxBlocks) blocks = maxBlocks;
    if (blocks < 1) blocks = 1;

    fused_kernel<<<blocks, 256>>>(x, out, n, vec_ok,
                                  a, W1, b1, W2, b2, Ww, bw, Wk, bk);
}

// round 13
// speedup vs baseline: 2.0239x; 1.2087x over previous
#include <cuda_runtime.h>
#include <cstdint>

// ---------------------------------------------------------------------------
// NeuralSplineFourierFilter: tiny MLP on scalar 'a' -> 16 knots + 18 control
// points -> degree-3 B-spline on a 256^3 grid.
//
// R10: ONE kernel, 1024-thread blocks (2/SM instead of 8/SM) so the per-block
// prelude (MLP + softmax + fp32 symbolic de Boor + bin table) is replicated
// 2x per SM instead of 8x — R9's 9us prelude cost was exactly this
// replication. Table built via a 2049-entry edge array (2 spline_at/thread).
// Hot loop unchanged: clamp-scale, LDS.64 (f_lo, f_hi), lerp.
// ---------------------------------------------------------------------------

#define NSEG   15
#define NBIN   2048
#define NEDGE  (NBIN + 1)
#define TPB    1024

#define KSCALE ((float)NBIN * 0.5773502691896258f)   // NBIN / sqrt(3)
#define TMAX   ((1.0f - 1e-4f) * (float)NBIN)

struct __align__(16) SmemLayout {
    float2 bins[NBIN];        // 16 KB: (f_lo, f_hi) per bin
    float  edge[NEDGE + 3];   // 8.2 KB: f at bin edges (build scratch)
    float4 segP[NSEG + 1];    // segment cubics, local coords u = x - k[s]
    float  segLo[16];
    float  knots[16];
    float  net[32];
    float  net2[32];
    float  klog[16];
    float  c[18];
};

__device__ __forceinline__ float spline_at(float xe, const SmemLayout& sm)
{
    int s = 0;
    #pragma unroll
    for (int i = 1; i < 16; ++i) s += (sm.knots[i] <= xe) ? 1 : 0;
    if (s > NSEG - 1) s = NSEG - 1;
    const float4 q = sm.segP[s];
    const float u = xe - sm.segLo[s];
    return fmaf(fmaf(fmaf(q.w, u, q.z), u, q.y), u, q.x);
}

__device__ __forceinline__ void build_tables(
    SmemLayout& sm, int t,
    const float* __restrict__ a_in,
    const float* __restrict__ W1, const float* __restrict__ b1,
    const float* __restrict__ W2, const float* __restrict__ b2,
    const float* __restrict__ Ww, const float* __restrict__ bw,
    const float* __restrict__ Wk, const float* __restrict__ bk)
{
    if (t < 32) {
        const float a = a_in[0];
        sm.net[t] = __sinf(fmaf(a, W1[t], b1[t]));
    }
    __syncthreads();
    if (t < 32) {
        float acc = b2[t];
        #pragma unroll
        for (int j = 0; j < 32; ++j) acc = fmaf(sm.net[j], W2[j * 32 + t], acc);
        sm.net2[t] = __sinf(acc);
    }
    __syncthreads();
    if (t < 17) {                       // control-point deltas -> c[1..17]
        float w = bw[t];
        #pragma unroll
        for (int j = 0; j < 32; ++j) w = fmaf(sm.net2[j], Ww[j * 17 + t], w);
        sm.c[t + 1] = w;
    }
    if (t >= 32 && t < 47) {            // knot logits, overlapped warp
        const int i = t - 32;
        float kk = bk[i];
        #pragma unroll
        for (int j = 0; j < 32; ++j) kk = fmaf(sm.net2[j], Wk[j * 15 + i], kk);
        sm.klog[i] = kk;
    }
    __syncthreads();
    if (t == 0) {                       // softmax + cumsum -> monotone knots
        float m = sm.klog[0];
        #pragma unroll
        for (int i = 1; i < 15; ++i) m = fmaxf(m, sm.klog[i]);
        float e[15], sum = 0.f;
        #pragma unroll
        for (int i = 0; i < 15; ++i) { e[i] = __expf(sm.klog[i] - m); sum += e[i]; }
        const float inv = 1.0f / sum;
        float cs = 0.f;
        sm.knots[0] = 0.f;
        #pragma unroll
        for (int i = 0; i < 15; ++i) { cs += e[i] * inv; sm.knots[i + 1] = cs; }
        sm.c[0] = 0.f;
    }
    __syncthreads();

    // Symbolic de Boor (fp32): exact cubic per segment in u = x - k[s].
    // Local coords keep every Horner term O(|c|): fp32 error ~1e-6, well
    // under the 1.7e-5 linear-table error.
    if (t < NSEG) {
        float T[22];
        #pragma unroll
        for (int i = 0; i < 3; ++i)  T[i] = 0.f;
        #pragma unroll
        for (int i = 0; i < 16; ++i) T[3 + i] = sm.knots[i];
        #pragma unroll
        for (int i = 19; i < 22; ++i) T[i] = 1.f;

        const int s = t;
        const float x0 = T[s + 3];

        float D[4][4];
        #pragma unroll
        for (int j = 0; j < 4; ++j) {
            D[j][0] = sm.c[s + j];
            D[j][1] = D[j][2] = D[j][3] = 0.f;
        }
        #pragma unroll
        for (int r = 1; r <= 3; ++r) {
            #pragma unroll
            for (int j = 3; j >= 1; --j) {
                if (j < r) continue;
                const float tlo = T[j + s];
                const float thi = T[j + 1 + s + 3 - r];
                const float A = 1.0f / (thi - tlo);
                const float B = A * (x0 - tlo);      // alpha(u) = A*u + B
                float nf[4];
                #pragma unroll
                for (int m2 = 0; m2 < 4; ++m2) {
                    const float dm  = D[j][m2] - D[j - 1][m2];
                    const float dm1 = (m2 > 0) ? (D[j][m2 - 1] - D[j - 1][m2 - 1]) : 0.f;
                    nf[m2] = fmaf(B, dm, fmaf(A, dm1, D[j - 1][m2]));
                }
                #pragma unroll
                for (int m2 = 0; m2 < 4; ++m2) D[j][m2] = nf[m2];
            }
        }
        sm.segP[s]  = make_float4(D[3][0], D[3][1], D[3][2], D[3][3]);
        sm.segLo[s] = x0;
    }
    __syncthreads();

    // Edge array: 2049 edges / 1024 threads = 2 spline_at per thread.
    for (int e = t; e < NEDGE; e += TPB)
        sm.edge[e] = spline_at((float)e * (1.0f / (float)NBIN), sm);
    __syncthreads();

    // Assemble float2 bins (one LDS.64 target per hot-loop access).
    for (int b = t; b < NBIN; b += TPB)
        sm.bins[b] = make_float2(sm.edge[b], sm.edge[b + 1]);
    __syncthreads();
}

__device__ __forceinline__ float eval_one(float xi, const float2* __restrict__ sBins)
{
    const float tt = fminf(fmaxf(xi * KSCALE, 0.0f), TMAX);
    const int   b  = (int)tt;
    const float fr = tt - (float)b;
    const float2 v = sBins[b];
    return fmaf(fr, v.y - v.x, v.x);
}

__global__ void __launch_bounds__(TPB)
fused_kernel(const float* __restrict__ x, float* __restrict__ out, int n,
             int vec_ok,
             const float* __restrict__ a_in,
             const float* __restrict__ W1, const float* __restrict__ b1,
             const float* __restrict__ W2, const float* __restrict__ b2,
             const float* __restrict__ Ww, const float* __restrict__ bw,
             const float* __restrict__ Wk, const float* __restrict__ bk)
{
    __shared__ SmemLayout sm;
    const int tid = threadIdx.x;
    build_tables(sm, tid, a_in, W1, b1, W2, b2, Ww, bw, Wk, bk);
    const float2* sBins = sm.bins;

    const int stride = gridDim.x * blockDim.x;

    if (vec_ok) {
        const int n4 = n >> 2;
        const float4* __restrict__ x4 = reinterpret_cast<const float4*>(x);
        float4* __restrict__ o4 = reinterpret_cast<float4*>(out);

        int i = blockIdx.x * blockDim.x + tid;
        for (; i + 3 * stride < n4; i += 4 * stride) {
            const float4 a0 = x4[i];
            const float4 a1 = x4[i + stride];
            const float4 a2 = x4[i + 2 * stride];
            const float4 a3 = x4[i + 3 * stride];
            float4 r0, r1, r2, r3;
            r0.x = eval_one(a0.x, sBins); r0.y = eval_one(a0.y, sBins);
            r0.z = eval_one(a0.z, sBins); r0.w = eval_one(a0.w, sBins);
            r1.x = eval_one(a1.x, sBins); r1.y = eval_one(a1.y, sBins);
            r1.z = eval_one(a1.z, sBins); r1.w = eval_one(a1.w, sBins);
            r2.x = eval_one(a2.x, sBins); r2.y = eval_one(a2.y, sBins);
            r2.z = eval_one(a2.z, sBins); r2.w = eval_one(a2.w, sBins);
            r3.x = eval_one(a3.x, sBins); r3.y = eval_one(a3.y, sBins);
            r3.z = eval_one(a3.z, sBins); r3.w = eval_one(a3.w, sBins);
            o4[i]              = r0;
            o4[i + stride]     = r1;
            o4[i + 2 * stride] = r2;
            o4[i + 3 * stride] = r3;
        }
        for (; i < n4; i += stride) {
            const float4 a = x4[i];
            float4 r;
            r.x = eval_one(a.x, sBins); r.y = eval_one(a.y, sBins);
            r.z = eval_one(a.z, sBins); r.w = eval_one(a.w, sBins);
            o4[i] = r;
        }
        // scalar tail (n % 4 != 0) — exact segment cubic, negligible count
        const float INV_SQRT3 = 0.5773502691896258f;
        for (int j = (n4 << 2) + blockIdx.x * blockDim.x + tid; j < n; j += stride) {
            const float xc = fminf(fmaxf(x[j] * INV_SQRT3, 0.0f), 0.99990000f);
            out[j] = spline_at(xc, sm);
        }
    } else {
        // misalignment fallback: all-scalar lerp loop
        for (int j = blockIdx.x * blockDim.x + tid; j < n; j += stride)
            out[j] = eval_one(x[j], sBins);
    }
}

// ---------------------------------------------------------------------------
extern "C" void kernel_launch(void* const* d_in, const int* in_sizes, int n_in,
                              void* d_out, int out_size)
{
    const float* x  = (const float*)d_in[0];
    const float* a  = (const float*)d_in[1];
    const float* W1 = (const float*)d_in[2];
    const float* b1 = (const float*)d_in[3];
    const float* W2 = (const float*)d_in[4];
    const float* b2 = (const float*)d_in[5];
    const float* Ww = (const float*)d_in[6];
    const float* bw = (const float*)d_in[7];
    const float* Wk = (const float*)d_in[8];
    const float* bk = (const float*)d_in[9];
    float* out = (float*)d_out;
    const int n = in_sizes[0];

    const int vec_ok =
        (((((uintptr_t)x) | ((uintptr_t)out)) & 0xF) == 0) ? 1 : 0;

    int blocks = 148 * 2;                       // one resident wave @1024 thr
    const int work_items = vec_ok ? (n + 3) / 4 : n;
    const int maxBlocks = (work_items + TPB - 1) / TPB;
    if (blocks > maxBlocks) blocks = maxBlocks;
    if (blocks < 1) blocks = 1;

    fused_kernel<<<blocks, TPB>>>(x, out, n, vec_ok,
                                  a, W1, b1, W2, b2, Ww, bw, Wk, bk);
}

// round 16
// speedup vs baseline: 2.0417x; 1.0088x over previous
#include <cuda_runtime.h>
#include <cstdint>

// ---------------------------------------------------------------------------
// NeuralSplineFourierFilter: tiny MLP on scalar 'a' -> 16 knots + 18 control
// points -> degree-3 B-spline on a 256^3 grid.
//
// R11: one fused kernel (R10 design), but 512-thread blocks with
// __launch_bounds__(512,2): same 2-blocks/SM prelude replication, yet 64
// regs/thread instead of 32 -> unroll-8 (8 front-batched LDG.128, 32
// elements in flight/warp). R10 was latency-bound (DRAM 38%, L1 58%,
// issue 31%, nothing saturated) because 1024-thread blocks capped regs at 32.
// ---------------------------------------------------------------------------

#define NSEG   15
#define NBIN   2048
#define NEDGE  (NBIN + 1)
#define TPB    512
#define UNROLL 8

#define KSCALE ((float)NBIN * 0.5773502691896258f)   // NBIN / sqrt(3)
#define TMAX   ((1.0f - 1e-4f) * (float)NBIN)

struct __align__(16) SmemLayout {
    float2 bins[NBIN];        // 16 KB: (f_lo, f_hi) per bin
    float  edge[NEDGE + 3];   // 8.2 KB: f at bin edges (build scratch)
    float4 segP[NSEG + 1];    // segment cubics, local coords u = x - k[s]
    float  segLo[16];
    float  knots[16];
    float  net[32];
    float  net2[32];
    float  klog[16];
    float  c[18];
};

__device__ __forceinline__ float spline_at(float xe, const SmemLayout& sm)
{
    int s = 0;
    #pragma unroll
    for (int i = 1; i < 16; ++i) s += (sm.knots[i] <= xe) ? 1 : 0;
    if (s > NSEG - 1) s = NSEG - 1;
    const float4 q = sm.segP[s];
    const float u = xe - sm.segLo[s];
    return fmaf(fmaf(fmaf(q.w, u, q.z), u, q.y), u, q.x);
}

__device__ __forceinline__ void build_tables(
    SmemLayout& sm, int t,
    const float* __restrict__ a_in,
    const float* __restrict__ W1, const float* __restrict__ b1,
    const float* __restrict__ W2, const float* __restrict__ b2,
    const float* __restrict__ Ww, const float* __restrict__ bw,
    const float* __restrict__ Wk, const float* __restrict__ bk)
{
    if (t < 32) {
        const float a = a_in[0];
        sm.net[t] = __sinf(fmaf(a, W1[t], b1[t]));
    }
    __syncthreads();
    if (t < 32) {
        float acc = b2[t];
        #pragma unroll
        for (int j = 0; j < 32; ++j) acc = fmaf(sm.net[j], W2[j * 32 + t], acc);
        sm.net2[t] = __sinf(acc);
    }
    __syncthreads();
    if (t < 17) {                       // control-point deltas -> c[1..17]
        float w = bw[t];
        #pragma unroll
        for (int j = 0; j < 32; ++j) w = fmaf(sm.net2[j], Ww[j * 17 + t], w);
        sm.c[t + 1] = w;
    }
    if (t >= 32 && t < 47) {            // knot logits, overlapped warp
        const int i = t - 32;
        float kk = bk[i];
        #pragma unroll
        for (int j = 0; j < 32; ++j) kk = fmaf(sm.net2[j], Wk[j * 15 + i], kk);
        sm.klog[i] = kk;
    }
    __syncthreads();
    if (t == 0) {                       // softmax + cumsum -> monotone knots
        float m = sm.klog[0];
        #pragma unroll
        for (int i = 1; i < 15; ++i) m = fmaxf(m, sm.klog[i]);
        float e[15], sum = 0.f;
        #pragma unroll
        for (int i = 0; i < 15; ++i) { e[i] = __expf(sm.klog[i] - m); sum += e[i]; }
        const float inv = 1.0f / sum;
        float cs = 0.f;
        sm.knots[0] = 0.f;
        #pragma unroll
        for (int i = 0; i < 15; ++i) { cs += e[i] * inv; sm.knots[i + 1] = cs; }
        sm.c[0] = 0.f;
    }
    __syncthreads();

    // Symbolic de Boor (fp32): exact cubic per segment in u = x - k[s].
    if (t < NSEG) {
        float T[22];
        #pragma unroll
        for (int i = 0; i < 3; ++i)  T[i] = 0.f;
        #pragma unroll
        for (int i = 0; i < 16; ++i) T[3 + i] = sm.knots[i];
        #pragma unroll
        for (int i = 19; i < 22; ++i) T[i] = 1.f;

        const int s = t;
        const float x0 = T[s + 3];

        float D[4][4];
        #pragma unroll
        for (int j = 0; j < 4; ++j) {
            D[j][0] = sm.c[s + j];
            D[j][1] = D[j][2] = D[j][3] = 0.f;
        }
        #pragma unroll
        for (int r = 1; r <= 3; ++r) {
            #pragma unroll
            for (int j = 3; j >= 1; --j) {
                if (j < r) continue;
                const float tlo = T[j + s];
                const float thi = T[j + 1 + s + 3 - r];
                const float A = 1.0f / (thi - tlo);
                const float B = A * (x0 - tlo);      // alpha(u) = A*u + B
                float nf[4];
                #pragma unroll
                for (int m2 = 0; m2 < 4; ++m2) {
                    const float dm  = D[j][m2] - D[j - 1][m2];
                    const float dm1 = (m2 > 0) ? (D[j][m2 - 1] - D[j - 1][m2 - 1]) : 0.f;
                    nf[m2] = fmaf(B, dm, fmaf(A, dm1, D[j - 1][m2]));
                }
                #pragma unroll
                for (int m2 = 0; m2 < 4; ++m2) D[j][m2] = nf[m2];
            }
        }
        sm.segP[s]  = make_float4(D[3][0], D[3][1], D[3][2], D[3][3]);
        sm.segLo[s] = x0;
    }
    __syncthreads();

    // Edge array: 2049 edges / 512 threads ≈ 4 spline_at per thread.
    for (int e = t; e < NEDGE; e += TPB)
        sm.edge[e] = spline_at((float)e * (1.0f / (float)NBIN), sm);
    __syncthreads();

    // Assemble float2 bins (one LDS.64 target per hot-loop access).
    for (int b = t; b < NBIN; b += TPB)
        sm.bins[b] = make_float2(sm.edge[b], sm.edge[b + 1]);
    __syncthreads();
}

__device__ __forceinline__ float eval_one(float xi, const float2* __restrict__ sBins)
{
    const float tt = fminf(fmaxf(xi * KSCALE, 0.0f), TMAX);
    const int   b  = (int)tt;
    const float fr = tt - (float)b;
    const float2 v = sBins[b];
    return fmaf(fr, v.y - v.x, v.x);
}

__global__ void __launch_bounds__(TPB, 2)
fused_kernel(const float* __restrict__ x, float* __restrict__ out, int n,
             int vec_ok,
             const float* __restrict__ a_in,
             const float* __restrict__ W1, const float* __restrict__ b1,
             const float* __restrict__ W2, const float* __restrict__ b2,
             const float* __restrict__ Ww, const float* __restrict__ bw,
             const float* __restrict__ Wk, const float* __restrict__ bk)
{
    __shared__ SmemLayout sm;
    const int tid = threadIdx.x;
    build_tables(sm, tid, a_in, W1, b1, W2, b2, Ww, bw, Wk, bk);
    const float2* sBins = sm.bins;

    const int stride = gridDim.x * blockDim.x;

    if (vec_ok) {
        const int n4 = n >> 2;
        const float4* __restrict__ x4 = reinterpret_cast<const float4*>(x);
        float4* __restrict__ o4 = reinterpret_cast<float4*>(out);

        int i = blockIdx.x * blockDim.x + tid;
        for (; i + (UNROLL - 1) * stride < n4; i += UNROLL * stride) {
            float4 a[UNROLL];
            #pragma unroll
            for (int u = 0; u < UNROLL; ++u) a[u] = x4[i + u * stride];
            float4 r[UNROLL];
            #pragma unroll
            for (int u = 0; u < UNROLL; ++u) {
                r[u].x = eval_one(a[u].x, sBins);
                r[u].y = eval_one(a[u].y, sBins);
                r[u].z = eval_one(a[u].z, sBins);
                r[u].w = eval_one(a[u].w, sBins);
            }
            #pragma unroll
            for (int u = 0; u < UNROLL; ++u) o4[i + u * stride] = r[u];
        }
        for (; i < n4; i += stride) {
            const float4 a = x4[i];
            float4 r;
            r.x = eval_one(a.x, sBins); r.y = eval_one(a.y, sBins);
            r.z = eval_one(a.z, sBins); r.w = eval_one(a.w, sBins);
            o4[i] = r;
        }
        // scalar tail (n % 4 != 0) — exact segment cubic, negligible count
        const float INV_SQRT3 = 0.5773502691896258f;
        for (int j = (n4 << 2) + blockIdx.x * blockDim.x + tid; j < n; j += stride) {
            const float xc = fminf(fmaxf(x[j] * INV_SQRT3, 0.0f), 0.99990000f);
            out[j] = spline_at(xc, sm);
        }
    } else {
        // misalignment fallback: all-scalar lerp loop
        for (int j = blockIdx.x * blockDim.x + tid; j < n; j += stride)
            out[j] = eval_one(x[j], sBins);
    }
}

// ---------------------------------------------------------------------------
extern "C" void kernel_launch(void* const* d_in, const int* in_sizes, int n_in,
                              void* d_out, int out_size)
{
    const float* x  = (const float*)d_in[0];
    const float* a  = (const float*)d_in[1];
    const float* W1 = (const float*)d_in[2];
    const float* b1 = (const float*)d_in[3];
    const float* W2 = (const float*)d_in[4];
    const float* b2 = (const float*)d_in[5];
    const float* Ww = (const float*)d_in[6];
    const float* bw = (const float*)d_in[7];
    const float* Wk = (const float*)d_in[8];
    const float* bk = (const float*)d_in[9];
    float* out = (float*)d_out;
    const int n = in_sizes[0];

    const int vec_ok =
        (((((uintptr_t)x) | ((uintptr_t)out)) & 0xF) == 0) ? 1 : 0;

    int blocks = 148 * 2;                       // one resident wave @512thr x2/SM
    const int work_items = vec_ok ? (n + 3) / 4 : n;
    const int maxBlocks = (work_items + TPB - 1) / TPB;
    if (blocks > maxBlocks) blocks = maxBlocks;
    if (blocks < 1) blocks = 1;

    fused_kernel<<<blocks, TPB>>>(x, out, n, vec_ok,
                                  a, W1, b1, W2, b2, Ww, bw, Wk, bk);
}

// round 17
// speedup vs baseline: 2.2326x; 1.0935x over previous
#include <cuda_runtime.h>
#include <cstdint>

// ---------------------------------------------------------------------------
// NeuralSplineFourierFilter: tiny MLP on scalar 'a' -> 16 knots + 18 control
// points -> degree-3 B-spline on a 256^3 grid.
//
// R12: R10 shape (one fused kernel, 1024-thread blocks, 2/SM, unroll-4 hot
// loop) + streaming cache hints (__ldcs/__stcs: keep 67MB of store traffic
// from churning L2 against the input stream) + 1024-bin table (halves the
// replicated prelude's edge build; interp error 7.4e-5, 13x under 1e-3).
// Hot loop: clamp-scale, LDS.64 (f_lo, f_hi), lerp.
// ---------------------------------------------------------------------------

#define NSEG   15
#define NBIN   1024
#define NEDGE  (NBIN + 1)
#define TPB    1024
#define UNROLL 4

#define KSCALE ((float)NBIN * 0.5773502691896258f)   // NBIN / sqrt(3)
#define TMAX   ((1.0f - 1e-4f) * (float)NBIN)

struct __align__(16) SmemLayout {
    float2 bins[NBIN];        // 8 KB: (f_lo, f_hi) per bin
    float  edge[NEDGE + 3];   // 4.1 KB: f at bin edges (build scratch)
    float4 segP[NSEG + 1];    // segment cubics, local coords u = x - k[s]
    float  segLo[16];
    float  knots[16];
    float  net[32];
    float  net2[32];
    float  klog[16];
    float  c[18];
};

__device__ __forceinline__ float spline_at(float xe, const SmemLayout& sm)
{
    int s = 0;
    #pragma unroll
    for (int i = 1; i < 16; ++i) s += (sm.knots[i] <= xe) ? 1 : 0;
    if (s > NSEG - 1) s = NSEG - 1;
    const float4 q = sm.segP[s];
    const float u = xe - sm.segLo[s];
    return fmaf(fmaf(fmaf(q.w, u, q.z), u, q.y), u, q.x);
}

__device__ __forceinline__ void build_tables(
    SmemLayout& sm, int t,
    const float* __restrict__ a_in,
    const float* __restrict__ W1, const float* __restrict__ b1,
    const float* __restrict__ W2, const float* __restrict__ b2,
    const float* __restrict__ Ww, const float* __restrict__ bw,
    const float* __restrict__ Wk, const float* __restrict__ bk)
{
    if (t < 32) {
        const float a = a_in[0];
        sm.net[t] = __sinf(fmaf(a, W1[t], b1[t]));
    }
    __syncthreads();
    if (t < 32) {
        float acc = b2[t];
        #pragma unroll
        for (int j = 0; j < 32; ++j) acc = fmaf(sm.net[j], W2[j * 32 + t], acc);
        sm.net2[t] = __sinf(acc);
    }
    __syncthreads();
    if (t < 17) {                       // control-point deltas -> c[1..17]
        float w = bw[t];
        #pragma unroll
        for (int j = 0; j < 32; ++j) w = fmaf(sm.net2[j], Ww[j * 17 + t], w);
        sm.c[t + 1] = w;
    }
    if (t >= 32 && t < 47) {            // knot logits, overlapped warp
        const int i = t - 32;
        float kk = bk[i];
        #pragma unroll
        for (int j = 0; j < 32; ++j) kk = fmaf(sm.net2[j], Wk[j * 15 + i], kk);
        sm.klog[i] = kk;
    }
    __syncthreads();
    if (t == 0) {                       // softmax + cumsum -> monotone knots
        float m = sm.klog[0];
        #pragma unroll
        for (int i = 1; i < 15; ++i) m = fmaxf(m, sm.klog[i]);
        float e[15], sum = 0.f;
        #pragma unroll
        for (int i = 0; i < 15; ++i) { e[i] = __expf(sm.klog[i] - m); sum += e[i]; }
        const float inv = 1.0f / sum;
        float cs = 0.f;
        sm.knots[0] = 0.f;
        #pragma unroll
        for (int i = 0; i < 15; ++i) { cs += e[i] * inv; sm.knots[i + 1] = cs; }
        sm.c[0] = 0.f;
    }
    __syncthreads();

    // Symbolic de Boor (fp32): exact cubic per segment in u = x - k[s].
    // Local coords keep every Horner term O(|c|): fp32 error ~1e-6.
    if (t < NSEG) {
        float T[22];
        #pragma unroll
        for (int i = 0; i < 3; ++i)  T[i] = 0.f;
        #pragma unroll
        for (int i = 0; i < 16; ++i) T[3 + i] = sm.knots[i];
        #pragma unroll
        for (int i = 19; i < 22; ++i) T[i] = 1.f;

        const int s = t;
        const float x0 = T[s + 3];

        float D[4][4];
        #pragma unroll
        for (int j = 0; j < 4; ++j) {
            D[j][0] = sm.c[s + j];
            D[j][1] = D[j][2] = D[j][3] = 0.f;
        }
        #pragma unroll
        for (int r = 1; r <= 3; ++r) {
            #pragma unroll
            for (int j = 3; j >= 1; --j) {
                if (j < r) continue;
                const float tlo = T[j + s];
                const float thi = T[j + 1 + s + 3 - r];
                const float A = 1.0f / (thi - tlo);
                const float B = A * (x0 - tlo);      // alpha(u) = A*u + B
                float nf[4];
                #pragma unroll
                for (int m2 = 0; m2 < 4; ++m2) {
                    const float dm  = D[j][m2] - D[j - 1][m2];
                    const float dm1 = (m2 > 0) ? (D[j][m2 - 1] - D[j - 1][m2 - 1]) : 0.f;
                    nf[m2] = fmaf(B, dm, fmaf(A, dm1, D[j - 1][m2]));
                }
                #pragma unroll
                for (int m2 = 0; m2 < 4; ++m2) D[j][m2] = nf[m2];
            }
        }
        sm.segP[s]  = make_float4(D[3][0], D[3][1], D[3][2], D[3][3]);
        sm.segLo[s] = x0;
    }
    __syncthreads();

    // Edge array: 1025 edges / 1024 threads = 1 spline_at per thread (+1).
    for (int e = t; e < NEDGE; e += TPB)
        sm.edge[e] = spline_at((float)e * (1.0f / (float)NBIN), sm);
    __syncthreads();

    // Assemble float2 bins (one LDS.64 target per hot-loop access).
    for (int b = t; b < NBIN; b += TPB)
        sm.bins[b] = make_float2(sm.edge[b], sm.edge[b + 1]);
    __syncthreads();
}

__device__ __forceinline__ float eval_one(float xi, const float2* __restrict__ sBins)
{
    const float tt = fminf(fmaxf(xi * KSCALE, 0.0f), TMAX);
    const int   b  = (int)tt;
    const float fr = tt - (float)b;
    const float2 v = sBins[b];
    return fmaf(fr, v.y - v.x, v.x);
}

__global__ void __launch_bounds__(TPB)
fused_kernel(const float* __restrict__ x, float* __restrict__ out, int n,
             int vec_ok,
             const float* __restrict__ a_in,
             const float* __restrict__ W1, const float* __restrict__ b1,
             const float* __restrict__ W2, const float* __restrict__ b2,
             const float* __restrict__ Ww, const float* __restrict__ bw,
             const float* __restrict__ Wk, const float* __restrict__ bk)
{
    __shared__ SmemLayout sm;
    const int tid = threadIdx.x;
    build_tables(sm, tid, a_in, W1, b1, W2, b2, Ww, bw, Wk, bk);
    const float2* sBins = sm.bins;

    const int stride = gridDim.x * blockDim.x;

    if (vec_ok) {
        const int n4 = n >> 2;
        const float4* __restrict__ x4 = reinterpret_cast<const float4*>(x);
        float4* __restrict__ o4 = reinterpret_cast<float4*>(out);

        int i = blockIdx.x * blockDim.x + tid;
        for (; i + (UNROLL - 1) * stride < n4; i += UNROLL * stride) {
            float4 a[UNROLL];
            #pragma unroll
            for (int u = 0; u < UNROLL; ++u) a[u] = __ldcs(&x4[i + u * stride]);
            float4 r[UNROLL];
            #pragma unroll
            for (int u = 0; u < UNROLL; ++u) {
                r[u].x = eval_one(a[u].x, sBins);
                r[u].y = eval_one(a[u].y, sBins);
                r[u].z = eval_one(a[u].z, sBins);
                r[u].w = eval_one(a[u].w, sBins);
            }
            #pragma unroll
            for (int u = 0; u < UNROLL; ++u) __stcs(&o4[i + u * stride], r[u]);
        }
        for (; i < n4; i += stride) {
            const float4 a = __ldcs(&x4[i]);
            float4 r;
            r.x = eval_one(a.x, sBins); r.y = eval_one(a.y, sBins);
            r.z = eval_one(a.z, sBins); r.w = eval_one(a.w, sBins);
            __stcs(&o4[i], r);
        }
        // scalar tail (n % 4 != 0) — exact segment cubic, negligible count
        const float INV_SQRT3 = 0.5773502691896258f;
        for (int j = (n4 << 2) + blockIdx.x * blockDim.x + tid; j < n; j += stride) {
            const float xc = fminf(fmaxf(x[j] * INV_SQRT3, 0.0f), 0.99990000f);
            out[j] = spline_at(xc, sm);
        }
    } else {
        // misalignment fallback: all-scalar lerp loop
        for (int j = blockIdx.x * blockDim.x + tid; j < n; j += stride)
            out[j] = eval_one(x[j], sBins);
    }
}

// ---------------------------------------------------------------------------
extern "C" void kernel_launch(void* const* d_in, const int* in_sizes, int n_in,
                              void* d_out, int out_size)
{
    const float* x  = (const float*)d_in[0];
    const float* a  = (const float*)d_in[1];
    const float* W1 = (const float*)d_in[2];
    const float* b1 = (const float*)d_in[3];
    const float* W2 = (const float*)d_in[4];
    const float* b2 = (const float*)d_in[5];
    const float* Ww = (const float*)d_in[6];
    const float* bw = (const float*)d_in[7];
    const float* Wk = (const float*)d_in[8];
    const float* bk = (const float*)d_in[9];
    float* out = (float*)d_out;
    const int n = in_sizes[0];

    const int vec_ok =
        (((((uintptr_t)x) | ((uintptr_t)out)) & 0xF) == 0) ? 1 : 0;

    int blocks = 148 * 2;                       // one resident wave @1024 thr
    const int work_items = vec_ok ? (n + 3) / 4 : n;
    const int maxBlocks = (work_items + TPB - 1) / TPB;
    if (blocks > maxBlocks) blocks = maxBlocks;
    if (blocks < 1) blocks = 1;

    fused_kernel<<<blocks, TPB>>>(x, out, n, vec_ok,
                                  a, W1, b1, W2, b2, Ww, bw, Wk, bk);
}